// round 12
// baseline (speedup 1.0000x reference)
#include <cuda_runtime.h>
#include <math.h>

// ---------------------------------------------------------------------------
// Attention1D: LN -> QKV GEMM -> 8x8 windowed attention w/ rel-pos bias -> out GEMM
// Shapes: B=32768, N=8, DIM=256, HEADS=8, DHEAD=32, K=256 everywhere.
// Round-1 strategy: fp32 FFMA SGEMM (128x128 CTA tile, 8x8 thread tile,
// double-buffered smem), LN fused into GEMM1 A-load, warp-per-(b,h) attention.
// ---------------------------------------------------------------------------

#define DIMQ      256
#define HEADS     8
#define NTOK      8
#define BATCH     32768
#define ROWS      (BATCH * NTOK)      // 262144 tokens
#define QKV_COLS  768

// Scratch (static device globals: allocation-free per harness rules)
__device__ float  g_qkv[(size_t)ROWS * QKV_COLS];   // 805 MB
__device__ float  g_att[(size_t)ROWS * DIMQ];       // 268 MB
__device__ float2 g_stats[ROWS];                    // 2 MB (mu, rsqrt(var+eps))

// ---------------------------------------------------------------------------
// Kernel 1: per-row LayerNorm statistics (one warp per 256-wide row)
// ---------------------------------------------------------------------------
__global__ void ln_stats_kernel(const float* __restrict__ x)
{
    const int warp = (blockIdx.x * blockDim.x + threadIdx.x) >> 5;
    const int lane = threadIdx.x & 31;
    if (warp >= ROWS) return;

    const float* xr = x + (size_t)warp * DIMQ;
    float4 a = *(const float4*)(xr + lane * 4);
    float4 b = *(const float4*)(xr + 128 + lane * 4);

    float s = a.x + a.y + a.z + a.w + b.x + b.y + b.z + b.w;
    float q = a.x*a.x + a.y*a.y + a.z*a.z + a.w*a.w
            + b.x*b.x + b.y*b.y + b.z*b.z + b.w*b.w;

    #pragma unroll
    for (int off = 16; off; off >>= 1) {
        s += __shfl_xor_sync(0xffffffffu, s, off);
        q += __shfl_xor_sync(0xffffffffu, q, off);
    }
    if (lane == 0) {
        const float mu  = s * (1.0f / DIMQ);
        const float var = q * (1.0f / DIMQ) - mu * mu;
        g_stats[warp] = make_float2(mu, rsqrtf(var + 1e-5f));
    }
}

// ---------------------------------------------------------------------------
// Kernel 2/4: SGEMM C[M,Nc] = A[M,K] * B[K,Nc], fp32.
// CTA tile 128x128, BK=8, 256 threads, 8x8 thread tile (split 4+4 rows/cols),
// double-buffered smem with register prefetch. All dims divide exactly:
// M=262144, K=256, Nc in {768, 256}.
// FUSE_LN: A is raw x; normalize on load using g_stats + ln_w/ln_b.
// ---------------------------------------------------------------------------
template <bool FUSE_LN>
__global__ void __launch_bounds__(256, 2)
sgemm128(const float* __restrict__ A, const float* __restrict__ B,
         float* __restrict__ C, int K, int Nc,
         const float* __restrict__ lw, const float* __restrict__ lb)
{
    __shared__ float As[2][8][132];   // padded: conflict-free transposed stores
    __shared__ float Bs[2][8][128];

    const int tid  = threadIdx.x;
    const int brow = blockIdx.y << 7;
    const int bcol = blockIdx.x << 7;

    // A-tile load mapping: 128 rows x 8 cols, float4 per thread (2 thr/row)
    const int arow = tid >> 1;
    const int acol = (tid & 1) << 2;
    const float* Ap = A + (size_t)(brow + arow) * K + acol;
    float mu = 0.f, rs = 0.f;
    if (FUSE_LN) {
        const float2 st = g_stats[brow + arow];
        mu = st.x; rs = st.y;
    }

    // B-tile load mapping: 8 rows x 128 cols, float4 per thread
    const int brw = tid >> 5;
    const int bcl = (tid & 31) << 2;
    const float* Bp = B + (size_t)brw * Nc + (bcol + bcl);

    // compute mapping: 16x16 threads, each 8x8 output (rows r0..+3,r1..+3)
    const int tx = tid & 15;
    const int ty = tid >> 4;
    const int r0 = ty << 2, r1 = 64 + (ty << 2);
    const int c0 = tx << 2, c1 = 64 + (tx << 2);

    float acc[8][8];
    #pragma unroll
    for (int i = 0; i < 8; ++i)
        #pragma unroll
        for (int j = 0; j < 8; ++j) acc[i][j] = 0.f;

    const int nk = K >> 3;   // 32 k-steps

    // ---- prologue: tile 0 ----
    {
        float4 av = *(const float4*)(Ap);
        if (FUSE_LN) {
            const float4 w4 = *(const float4*)(lw + acol);
            const float4 b4 = *(const float4*)(lb + acol);
            av.x = (av.x - mu) * rs * w4.x + b4.x;
            av.y = (av.y - mu) * rs * w4.y + b4.y;
            av.z = (av.z - mu) * rs * w4.z + b4.z;
            av.w = (av.w - mu) * rs * w4.w + b4.w;
        }
        const float4 bv = *(const float4*)(Bp);
        As[0][acol + 0][arow] = av.x;
        As[0][acol + 1][arow] = av.y;
        As[0][acol + 2][arow] = av.z;
        As[0][acol + 3][arow] = av.w;
        *(float4*)&Bs[0][brw][bcl] = bv;
    }
    __syncthreads();

    int buf = 0;
    for (int kt = 0; kt < nk; ++kt) {
        float4 nav, nbv;
        if (kt + 1 < nk) {
            nav = *(const float4*)(Ap + (kt + 1) * 8);
            if (FUSE_LN) {
                const float4 w4 = *(const float4*)(lw + (kt + 1) * 8 + acol);
                const float4 b4 = *(const float4*)(lb + (kt + 1) * 8 + acol);
                nav.x = (nav.x - mu) * rs * w4.x + b4.x;
                nav.y = (nav.y - mu) * rs * w4.y + b4.y;
                nav.z = (nav.z - mu) * rs * w4.z + b4.z;
                nav.w = (nav.w - mu) * rs * w4.w + b4.w;
            }
            nbv = *(const float4*)(Bp + (size_t)(kt + 1) * 8 * Nc);
        }

        #pragma unroll
        for (int kk = 0; kk < 8; ++kk) {
            float a[8], b[8];
            *(float4*)&a[0] = *(const float4*)&As[buf][kk][r0];
            *(float4*)&a[4] = *(const float4*)&As[buf][kk][r1];
            *(float4*)&b[0] = *(const float4*)&Bs[buf][kk][c0];
            *(float4*)&b[4] = *(const float4*)&Bs[buf][kk][c1];
            #pragma unroll
            for (int i = 0; i < 8; ++i)
                #pragma unroll
                for (int j = 0; j < 8; ++j)
                    acc[i][j] = fmaf(a[i], b[j], acc[i][j]);
        }

        if (kt + 1 < nk) {
            const int nb = buf ^ 1;
            As[nb][acol + 0][arow] = nav.x;
            As[nb][acol + 1][arow] = nav.y;
            As[nb][acol + 2][arow] = nav.z;
            As[nb][acol + 3][arow] = nav.w;
            *(float4*)&Bs[nb][brw][bcl] = nbv;
            __syncthreads();
        }
        buf ^= 1;
    }

    // ---- epilogue ----
    float* Cp = C + (size_t)brow * Nc + bcol;
    #pragma unroll
    for (int i = 0; i < 8; ++i) {
        const int row = (i < 4) ? (r0 + i) : (r1 + i - 4);
        float4 v0 = make_float4(acc[i][0], acc[i][1], acc[i][2], acc[i][3]);
        float4 v1 = make_float4(acc[i][4], acc[i][5], acc[i][6], acc[i][7]);
        *(float4*)(Cp + (size_t)row * Nc + c0) = v0;
        *(float4*)(Cp + (size_t)row * Nc + c1) = v1;
    }
}

// ---------------------------------------------------------------------------
// Kernel 3: attention. One warp per (batch, head). lane = d (0..31).
// qkv layout: row = token (b*8+n), cols: q[0:256) k[256:512) v[512:768),
// head h at offset h*32. Bias index recomputed analytically:
//   idx(i,j) = (i>=1 && j>=1) ? i-j+6 : 13   (WINDOW=7, REGS=1)
// ---------------------------------------------------------------------------
__global__ void attn_kernel(const float* __restrict__ btab)
{
    const int gw   = (blockIdx.x * blockDim.x + threadIdx.x) >> 5;
    const int lane = threadIdx.x & 31;
    if (gw >= BATCH * HEADS) return;
    const int b = gw >> 3;
    const int h = gw & 7;

    const float* base = g_qkv + (size_t)b * NTOK * QKV_COLS + h * 32 + lane;

    float kv[8], vv[8];
    #pragma unroll
    for (int n = 0; n < 8; ++n) {
        kv[n] = base[n * QKV_COLS + 256];
        vv[n] = base[n * QKV_COLS + 512];
    }

    const float scale = 0.1767766952966369f;  // 32^-0.5

    #pragma unroll
    for (int i = 0; i < 8; ++i) {
        const float qv = base[i * QKV_COLS] * scale;
        float p[8];
        #pragma unroll
        for (int j = 0; j < 8; ++j) {
            float t = qv * kv[j];
            #pragma unroll
            for (int off = 16; off; off >>= 1)
                t += __shfl_xor_sync(0xffffffffu, t, off);
            const int idx = (i >= 1 && j >= 1) ? (i - j + 6) : 13;
            p[j] = t + btab[idx * HEADS + h];
        }
        float m = p[0];
        #pragma unroll
        for (int j = 1; j < 8; ++j) m = fmaxf(m, p[j]);
        float s = 0.f;
        #pragma unroll
        for (int j = 0; j < 8; ++j) { p[j] = expf(p[j] - m); s += p[j]; }
        const float inv = 1.0f / s;
        float o = 0.f;
        #pragma unroll
        for (int j = 0; j < 8; ++j) o = fmaf(p[j], vv[j], o);
        g_att[((size_t)b * NTOK + i) * DIMQ + h * 32 + lane] = o * inv;
    }
}

// ---------------------------------------------------------------------------
// Launch: inputs per metadata order:
// 0:x 1:ln_w 2:ln_b 3:w_qkv 4:w_out 5:rel_bias_table 6:rel_pos_indices(unused)
// ---------------------------------------------------------------------------
extern "C" void kernel_launch(void* const* d_in, const int* in_sizes, int n_in,
                              void* d_out, int out_size)
{
    const float* x    = (const float*)d_in[0];
    const float* lw   = (const float*)d_in[1];
    const float* lb   = (const float*)d_in[2];
    const float* wqkv = (const float*)d_in[3];
    const float* wout = (const float*)d_in[4];
    const float* btab = (const float*)d_in[5];
    float* out = (float*)d_out;

    float* qkv = nullptr;
    float* att = nullptr;
    cudaGetSymbolAddress((void**)&qkv, g_qkv);
    cudaGetSymbolAddress((void**)&att, g_att);

    // 1) LayerNorm statistics (262144 warps)
    ln_stats_kernel<<<32768, 256>>>(x);

    // 2) QKV GEMM with fused LN: [262144,256] x [256,768]
    {
        dim3 grid(QKV_COLS / 128, ROWS / 128);   // (6, 2048)
        sgemm128<true><<<grid, 256>>>(x, wqkv, qkv, DIMQ, QKV_COLS, lw, lb);
    }

    // 3) Attention (one warp per (b,h))
    attn_kernel<<<32768, 256>>>(btab);

    // 4) Output projection: [262144,256] x [256,256]
    {
        dim3 grid(DIMQ / 128, ROWS / 128);       // (2, 2048)
        sgemm128<false><<<grid, 256>>>(att, wout, out, DIMQ, DIMQ,
                                       nullptr, nullptr);
    }
}

// round 13
// speedup vs baseline: 1.0005x; 1.0005x over previous
#include <cuda_runtime.h>
#include <math.h>

// ---------------------------------------------------------------------------
// Attention1D: LN -> QKV GEMM -> 8x8 windowed attention w/ rel-pos bias -> out GEMM
// Shapes: B=32768, N=8, DIM=256, HEADS=8, DHEAD=32, K=256 everywhere.
// Round-1 strategy: fp32 FFMA SGEMM (128x128 CTA tile, 8x8 thread tile,
// double-buffered smem), LN fused into GEMM1 A-load, warp-per-(b,h) attention.
// ---------------------------------------------------------------------------

#define DIMQ      256
#define HEADS     8
#define NTOK      8
#define BATCH     32768
#define ROWS      (BATCH * NTOK)      // 262144 tokens
#define QKV_COLS  768

// Scratch (static device globals: allocation-free per harness rules)
__device__ float  g_qkv[(size_t)ROWS * QKV_COLS];   // 805 MB
__device__ float  g_att[(size_t)ROWS * DIMQ];       // 268 MB
__device__ float2 g_stats[ROWS];                    // 2 MB (mu, rsqrt(var+eps))

// ---------------------------------------------------------------------------
// Kernel 1: per-row LayerNorm statistics (one warp per 256-wide row)
// ---------------------------------------------------------------------------
__global__ void ln_stats_kernel(const float* __restrict__ x)
{
    const int warp = (blockIdx.x * blockDim.x + threadIdx.x) >> 5;
    const int lane = threadIdx.x & 31;
    if (warp >= ROWS) return;

    const float* xr = x + (size_t)warp * DIMQ;
    float4 a = *(const float4*)(xr + lane * 4);
    float4 b = *(const float4*)(xr + 128 + lane * 4);

    float s = a.x + a.y + a.z + a.w + b.x + b.y + b.z + b.w;
    float q = a.x*a.x + a.y*a.y + a.z*a.z + a.w*a.w
            + b.x*b.x + b.y*b.y + b.z*b.z + b.w*b.w;

    #pragma unroll
    for (int off = 16; off; off >>= 1) {
        s += __shfl_xor_sync(0xffffffffu, s, off);
        q += __shfl_xor_sync(0xffffffffu, q, off);
    }
    if (lane == 0) {
        const float mu  = s * (1.0f / DIMQ);
        const float var = q * (1.0f / DIMQ) - mu * mu;
        g_stats[warp] = make_float2(mu, rsqrtf(var + 1e-5f));
    }
}

// ---------------------------------------------------------------------------
// Kernel 2/4: SGEMM C[M,Nc] = A[M,K] * B[K,Nc], fp32.
// CTA tile 128x128, BK=8, 256 threads, 8x8 thread tile (split 4+4 rows/cols),
// double-buffered smem with register prefetch. All dims divide exactly:
// M=262144, K=256, Nc in {768, 256}.
// FUSE_LN: A is raw x; normalize on load using g_stats + ln_w/ln_b.
// ---------------------------------------------------------------------------
template <bool FUSE_LN>
__global__ void __launch_bounds__(256, 2)
sgemm128(const float* __restrict__ A, const float* __restrict__ B,
         float* __restrict__ C, int K, int Nc,
         const float* __restrict__ lw, const float* __restrict__ lb)
{
    __shared__ float As[2][8][132];   // padded: conflict-free transposed stores
    __shared__ float Bs[2][8][128];

    const int tid  = threadIdx.x;
    const int brow = blockIdx.y << 7;
    const int bcol = blockIdx.x << 7;

    // A-tile load mapping: 128 rows x 8 cols, float4 per thread (2 thr/row)
    const int arow = tid >> 1;
    const int acol = (tid & 1) << 2;
    const float* Ap = A + (size_t)(brow + arow) * K + acol;
    float mu = 0.f, rs = 0.f;
    if (FUSE_LN) {
        const float2 st = g_stats[brow + arow];
        mu = st.x; rs = st.y;
    }

    // B-tile load mapping: 8 rows x 128 cols, float4 per thread
    const int brw = tid >> 5;
    const int bcl = (tid & 31) << 2;
    const float* Bp = B + (size_t)brw * Nc + (bcol + bcl);

    // compute mapping: 16x16 threads, each 8x8 output (rows r0..+3,r1..+3)
    const int tx = tid & 15;
    const int ty = tid >> 4;
    const int r0 = ty << 2, r1 = 64 + (ty << 2);
    const int c0 = tx << 2, c1 = 64 + (tx << 2);

    float acc[8][8];
    #pragma unroll
    for (int i = 0; i < 8; ++i)
        #pragma unroll
        for (int j = 0; j < 8; ++j) acc[i][j] = 0.f;

    const int nk = K >> 3;   // 32 k-steps

    // ---- prologue: tile 0 ----
    {
        float4 av = *(const float4*)(Ap);
        if (FUSE_LN) {
            const float4 w4 = *(const float4*)(lw + acol);
            const float4 b4 = *(const float4*)(lb + acol);
            av.x = (av.x - mu) * rs * w4.x + b4.x;
            av.y = (av.y - mu) * rs * w4.y + b4.y;
            av.z = (av.z - mu) * rs * w4.z + b4.z;
            av.w = (av.w - mu) * rs * w4.w + b4.w;
        }
        const float4 bv = *(const float4*)(Bp);
        As[0][acol + 0][arow] = av.x;
        As[0][acol + 1][arow] = av.y;
        As[0][acol + 2][arow] = av.z;
        As[0][acol + 3][arow] = av.w;
        *(float4*)&Bs[0][brw][bcl] = bv;
    }
    __syncthreads();

    int buf = 0;
    for (int kt = 0; kt < nk; ++kt) {
        float4 nav, nbv;
        if (kt + 1 < nk) {
            nav = *(const float4*)(Ap + (kt + 1) * 8);
            if (FUSE_LN) {
                const float4 w4 = *(const float4*)(lw + (kt + 1) * 8 + acol);
                const float4 b4 = *(const float4*)(lb + (kt + 1) * 8 + acol);
                nav.x = (nav.x - mu) * rs * w4.x + b4.x;
                nav.y = (nav.y - mu) * rs * w4.y + b4.y;
                nav.z = (nav.z - mu) * rs * w4.z + b4.z;
                nav.w = (nav.w - mu) * rs * w4.w + b4.w;
            }
            nbv = *(const float4*)(Bp + (size_t)(kt + 1) * 8 * Nc);
        }

        #pragma unroll
        for (int kk = 0; kk < 8; ++kk) {
            float a[8], b[8];
            *(float4*)&a[0] = *(const float4*)&As[buf][kk][r0];
            *(float4*)&a[4] = *(const float4*)&As[buf][kk][r1];
            *(float4*)&b[0] = *(const float4*)&Bs[buf][kk][c0];
            *(float4*)&b[4] = *(const float4*)&Bs[buf][kk][c1];
            #pragma unroll
            for (int i = 0; i < 8; ++i)
                #pragma unroll
                for (int j = 0; j < 8; ++j)
                    acc[i][j] = fmaf(a[i], b[j], acc[i][j]);
        }

        if (kt + 1 < nk) {
            const int nb = buf ^ 1;
            As[nb][acol + 0][arow] = nav.x;
            As[nb][acol + 1][arow] = nav.y;
            As[nb][acol + 2][arow] = nav.z;
            As[nb][acol + 3][arow] = nav.w;
            *(float4*)&Bs[nb][brw][bcl] = nbv;
            __syncthreads();
        }
        buf ^= 1;
    }

    // ---- epilogue ----
    float* Cp = C + (size_t)brow * Nc + bcol;
    #pragma unroll
    for (int i = 0; i < 8; ++i) {
        const int row = (i < 4) ? (r0 + i) : (r1 + i - 4);
        float4 v0 = make_float4(acc[i][0], acc[i][1], acc[i][2], acc[i][3]);
        float4 v1 = make_float4(acc[i][4], acc[i][5], acc[i][6], acc[i][7]);
        *(float4*)(Cp + (size_t)row * Nc + c0) = v0;
        *(float4*)(Cp + (size_t)row * Nc + c1) = v1;
    }
}

// ---------------------------------------------------------------------------
// Kernel 3: attention. One warp per (batch, head). lane = d (0..31).
// qkv layout: row = token (b*8+n), cols: q[0:256) k[256:512) v[512:768),
// head h at offset h*32. Bias index recomputed analytically:
//   idx(i,j) = (i>=1 && j>=1) ? i-j+6 : 13   (WINDOW=7, REGS=1)
// ---------------------------------------------------------------------------
__global__ void attn_kernel(const float* __restrict__ btab)
{
    const int gw   = (blockIdx.x * blockDim.x + threadIdx.x) >> 5;
    const int lane = threadIdx.x & 31;
    if (gw >= BATCH * HEADS) return;
    const int b = gw >> 3;
    const int h = gw & 7;

    const float* base = g_qkv + (size_t)b * NTOK * QKV_COLS + h * 32 + lane;

    float kv[8], vv[8];
    #pragma unroll
    for (int n = 0; n < 8; ++n) {
        kv[n] = base[n * QKV_COLS + 256];
        vv[n] = base[n * QKV_COLS + 512];
    }

    const float scale = 0.1767766952966369f;  // 32^-0.5

    #pragma unroll
    for (int i = 0; i < 8; ++i) {
        const float qv = base[i * QKV_COLS] * scale;
        float p[8];
        #pragma unroll
        for (int j = 0; j < 8; ++j) {
            float t = qv * kv[j];
            #pragma unroll
            for (int off = 16; off; off >>= 1)
                t += __shfl_xor_sync(0xffffffffu, t, off);
            const int idx = (i >= 1 && j >= 1) ? (i - j + 6) : 13;
            p[j] = t + btab[idx * HEADS + h];
        }
        float m = p[0];
        #pragma unroll
        for (int j = 1; j < 8; ++j) m = fmaxf(m, p[j]);
        float s = 0.f;
        #pragma unroll
        for (int j = 0; j < 8; ++j) { p[j] = expf(p[j] - m); s += p[j]; }
        const float inv = 1.0f / s;
        float o = 0.f;
        #pragma unroll
        for (int j = 0; j < 8; ++j) o = fmaf(p[j], vv[j], o);
        g_att[((size_t)b * NTOK + i) * DIMQ + h * 32 + lane] = o * inv;
    }
}

// ---------------------------------------------------------------------------
// Launch: inputs per metadata order:
// 0:x 1:ln_w 2:ln_b 3:w_qkv 4:w_out 5:rel_bias_table 6:rel_pos_indices(unused)
// ---------------------------------------------------------------------------
extern "C" void kernel_launch(void* const* d_in, const int* in_sizes, int n_in,
                              void* d_out, int out_size)
{
    const float* x    = (const float*)d_in[0];
    const float* lw   = (const float*)d_in[1];
    const float* lb   = (const float*)d_in[2];
    const float* wqkv = (const float*)d_in[3];
    const float* wout = (const float*)d_in[4];
    const float* btab = (const float*)d_in[5];
    float* out = (float*)d_out;

    float* qkv = nullptr;
    float* att = nullptr;
    cudaGetSymbolAddress((void**)&qkv, g_qkv);
    cudaGetSymbolAddress((void**)&att, g_att);

    // 1) LayerNorm statistics (262144 warps)
    ln_stats_kernel<<<32768, 256>>>(x);

    // 2) QKV GEMM with fused LN: [262144,256] x [256,768]
    {
        dim3 grid(QKV_COLS / 128, ROWS / 128);   // (6, 2048)
        sgemm128<true><<<grid, 256>>>(x, wqkv, qkv, DIMQ, QKV_COLS, lw, lb);
    }

    // 3) Attention (one warp per (b,h))
    attn_kernel<<<32768, 256>>>(btab);

    // 4) Output projection: [262144,256] x [256,256]
    {
        dim3 grid(DIMQ / 128, ROWS / 128);       // (2, 2048)
        sgemm128<false><<<grid, 256>>>(att, wout, out, DIMQ, DIMQ,
                                       nullptr, nullptr);
    }
}

// round 15
// speedup vs baseline: 1.7710x; 1.7702x over previous
#include <cuda_runtime.h>
#include <cuda_bf16.h>
#include <math.h>
#include <stdint.h>

// ---------------------------------------------------------------------------
// Attention1D on GB300 (sm_103 portable PTX path):
//   bf16 3-split GEMMs on mma.sync.m16n8k16 (HMMA, fp32 accum)
//   1) ln_split : LayerNorm(x) -> bf16 hi/lo               [262144,256]
//   2) wprep    : w^T -> bf16 hi/lo (K-major)               (tiny)
//   3) gemm_mma : qkv = xn @ w_qkv   -> fp32 [262144,768]
//   4) attn     : 8x8 windowed softmax + rel bias -> bf16 hi/lo
//   5) gemm_mma : out = att @ w_out  -> fp32 [262144,256]
// C = (Ahi+Alo)(Bhi+Blo) - AloBlo;  AloBlo ~ 2^-16 rel, dropped.
// ---------------------------------------------------------------------------

#define DIMQ      256
#define HEADS     8
#define NTOK      8
#define BATCH     32768
#define ROWS      (BATCH * NTOK)      // 262144
#define QKV_COLS  768
#define KDIM      256

// ----- scratch (device globals: allocation-free) -----
__device__ float          g_qkv[(size_t)ROWS * QKV_COLS];   // 805 MB fp32
__device__ __nv_bfloat16  g_xhi[(size_t)ROWS * KDIM];
__device__ __nv_bfloat16  g_xlo[(size_t)ROWS * KDIM];
__device__ __nv_bfloat16  g_ahi[(size_t)ROWS * KDIM];
__device__ __nv_bfloat16  g_alo[(size_t)ROWS * KDIM];
__device__ __nv_bfloat16  g_wq_hi[QKV_COLS * KDIM];         // w_qkv^T, K-major
__device__ __nv_bfloat16  g_wq_lo[QKV_COLS * KDIM];
__device__ __nv_bfloat16  g_wo_hi[DIMQ * KDIM];             // w_out^T, K-major
__device__ __nv_bfloat16  g_wo_lo[DIMQ * KDIM];

// ---------------------------------------------------------------------------
// helpers
// ---------------------------------------------------------------------------
__device__ __forceinline__ uint32_t smem_u32(const void* p) {
    uint32_t a;
    asm("{ .reg .u64 t; cvta.to.shared.u64 t, %1; cvt.u32.u64 %0, t; }"
        : "=r"(a) : "l"(p));
    return a;
}

__device__ __forceinline__ void cp16(uint32_t dst, const void* src) {
    asm volatile("cp.async.cg.shared.global [%0], [%1], 16;"
                 :: "r"(dst), "l"(src) : "memory");
}

#define LDSM4(r0, r1, r2, r3, addr)                                            \
    asm volatile("ldmatrix.sync.aligned.m8n8.x4.shared.b16 {%0,%1,%2,%3}, [%4];" \
                 : "=r"(r0), "=r"(r1), "=r"(r2), "=r"(r3) : "r"(addr))

#define MMA16816(d, a0, a1, a2, a3, b0, b1)                                    \
    asm volatile("mma.sync.aligned.m16n8k16.row.col.f32.bf16.bf16.f32 "        \
                 "{%0,%1,%2,%3}, {%4,%5,%6,%7}, {%8,%9}, {%0,%1,%2,%3};"       \
                 : "+f"((d)[0]), "+f"((d)[1]), "+f"((d)[2]), "+f"((d)[3])      \
                 : "r"(a0), "r"(a1), "r"(a2), "r"(a3), "r"(b0), "r"(b1))

// ---------------------------------------------------------------------------
// GEMM: C[128 x 128 tile] = (Ahi+Alo)[*,256] @ (Bhi+Blo)^T  (B given as
// Bt[n][k], K-major, row stride KDIM). fp32 output.
// 256 threads = 8 warps in 2(row) x 4(col); warp tile 64x32.
// BK=32, double-buffered cp.async; smem rows padded to 80B (conflict-free
// ldmatrix: banks r*20 mod 32 distinct for r=0..7).
// ---------------------------------------------------------------------------
#define SROWB     80                       // smem row stride (bytes)
#define TILE_B    (128 * SROWB)            // 10240 B per operand tile
#define STAGE_B   (4 * TILE_B)             // Ahi,Alo,Bhi,Blo
#define GEMM_SMEM (2 * STAGE_B)            // 81920 B

__global__ void __launch_bounds__(256)
gemm_mma(const __nv_bfloat16* __restrict__ Ahi, const __nv_bfloat16* __restrict__ Alo,
         const __nv_bfloat16* __restrict__ Bhi, const __nv_bfloat16* __restrict__ Blo,
         float* __restrict__ C, int Nc)
{
    extern __shared__ __align__(128) char smem[];
    const int tid  = threadIdx.x;
    const int lane = tid & 31;
    const int wid  = tid >> 5;
    const int warp_m = (wid & 1) * 64;
    const int warp_n = (wid >> 1) * 32;
    const uint32_t sb = smem_u32(smem);

    const size_t brow = (size_t)blockIdx.y * 128;
    const size_t bcol = (size_t)blockIdx.x * 128;

    const char* gAh = (const char*)(Ahi + brow * KDIM);
    const char* gAl = (const char*)(Alo + brow * KDIM);
    const char* gBh = (const char*)(Bhi + bcol * KDIM);
    const char* gBl = (const char*)(Blo + bcol * KDIM);

    // per-thread cp.async mapping: 512 16B-chunks per tile, 2 per thread
    const int cA = tid,        rA = cA >> 2, hA = cA & 3;
    const int cB = 256 + tid,  rB = cB >> 2, hB = cB & 3;
    const uint32_t sof0 = (uint32_t)(rA * SROWB + hA * 16);
    const uint32_t sof1 = (uint32_t)(rB * SROWB + hB * 16);
    const size_t   gof0 = (size_t)rA * (KDIM * 2) + hA * 16;
    const size_t   gof1 = (size_t)rB * (KDIM * 2) + hB * 16;

    float acc[4][4][4];
    #pragma unroll
    for (int i = 0; i < 4; ++i)
        #pragma unroll
        for (int j = 0; j < 4; ++j)
            #pragma unroll
            for (int r = 0; r < 4; ++r) acc[i][j][r] = 0.f;

    // ---- prologue: stage 0 ----
    {
        const uint32_t s = sb;
        cp16(s + 0 * TILE_B + sof0, gAh + gof0);  cp16(s + 0 * TILE_B + sof1, gAh + gof1);
        cp16(s + 1 * TILE_B + sof0, gAl + gof0);  cp16(s + 1 * TILE_B + sof1, gAl + gof1);
        cp16(s + 2 * TILE_B + sof0, gBh + gof0);  cp16(s + 2 * TILE_B + sof1, gBh + gof1);
        cp16(s + 3 * TILE_B + sof0, gBl + gof0);  cp16(s + 3 * TILE_B + sof1, gBl + gof1);
        asm volatile("cp.async.commit_group;" ::: "memory");
    }

    int buf = 0;
    for (int kt = 0; kt < 8; ++kt) {
        asm volatile("cp.async.wait_group 0;" ::: "memory");
        __syncthreads();   // stage `buf` visible; all warps done with buf^1

        if (kt < 7) {
            const uint32_t s = sb + (buf ^ 1) * STAGE_B;
            const size_t ko = (size_t)(kt + 1) * 64;
            cp16(s + 0*TILE_B + sof0, gAh + gof0 + ko);  cp16(s + 0*TILE_B + sof1, gAh + gof1 + ko);
            cp16(s + 1*TILE_B + sof0, gAl + gof0 + ko);  cp16(s + 1*TILE_B + sof1, gAl + gof1 + ko);
            cp16(s + 2*TILE_B + sof0, gBh + gof0 + ko);  cp16(s + 2*TILE_B + sof1, gBh + gof1 + ko);
            cp16(s + 3*TILE_B + sof0, gBl + gof0 + ko);  cp16(s + 3*TILE_B + sof1, gBl + gof1 + ko);
            asm volatile("cp.async.commit_group;" ::: "memory");
        }

        const uint32_t sbase = sb + buf * STAGE_B;

        #pragma unroll
        for (int ks = 0; ks < 2; ++ks) {
            // B fragments: 4 n8 tiles x {b0,b1}, hi and lo
            uint32_t bh[4][2], bl[4][2];
            #pragma unroll
            for (int p = 0; p < 2; ++p) {
                const int g   = lane >> 3;
                const int row = warp_n + p * 16 + (g >> 1) * 8 + (lane & 7);
                const int chk = 2 * ks + (g & 1);
                const uint32_t a = sbase + 2 * TILE_B + row * SROWB + chk * 16;
                LDSM4(bh[2*p][0], bh[2*p][1], bh[2*p+1][0], bh[2*p+1][1], a);
                LDSM4(bl[2*p][0], bl[2*p][1], bl[2*p+1][0], bl[2*p+1][1], a + TILE_B);
            }
            #pragma unroll
            for (int mt = 0; mt < 4; ++mt) {
                const int row = warp_m + mt * 16 + (lane & 15);
                const int chk = 2 * ks + (lane >> 4);
                const uint32_t a = sbase + row * SROWB + chk * 16;
                uint32_t ah0, ah1, ah2, ah3, al0, al1, al2, al3;
                LDSM4(ah0, ah1, ah2, ah3, a);
                LDSM4(al0, al1, al2, al3, a + TILE_B);
                #pragma unroll
                for (int nt = 0; nt < 4; ++nt) {
                    MMA16816(acc[mt][nt], ah0, ah1, ah2, ah3, bh[nt][0], bh[nt][1]);
                    MMA16816(acc[mt][nt], ah0, ah1, ah2, ah3, bl[nt][0], bl[nt][1]);
                    MMA16816(acc[mt][nt], al0, al1, al2, al3, bh[nt][0], bh[nt][1]);
                }
            }
        }
        buf ^= 1;
    }

    // ---- epilogue ----
    float* Cw = C + (brow + warp_m) * (size_t)Nc + bcol + warp_n;
    const int gr = lane >> 2;
    const int gc = (lane & 3) * 2;
    #pragma unroll
    for (int mt = 0; mt < 4; ++mt) {
        #pragma unroll
        for (int nt = 0; nt < 4; ++nt) {
            float* p0 = Cw + (size_t)(mt * 16 + gr) * Nc + nt * 8 + gc;
            *(float2*)p0            = make_float2(acc[mt][nt][0], acc[mt][nt][1]);
            *(float2*)(p0 + 8 * Nc) = make_float2(acc[mt][nt][2], acc[mt][nt][3]);
        }
    }
}

// ---------------------------------------------------------------------------
// LayerNorm + bf16 hi/lo split. One warp per 256-wide row.
// ---------------------------------------------------------------------------
__global__ void ln_split_kernel(const float* __restrict__ x,
                                const float* __restrict__ lw,
                                const float* __restrict__ lb)
{
    const int warp = (blockIdx.x * blockDim.x + threadIdx.x) >> 5;
    const int lane = threadIdx.x & 31;
    if (warp >= ROWS) return;

    const float* xr = x + (size_t)warp * DIMQ + lane * 8;
    float v[8];
    *(float4*)&v[0] = *(const float4*)xr;
    *(float4*)&v[4] = *(const float4*)(xr + 4);

    float s = 0.f, q = 0.f;
    #pragma unroll
    for (int i = 0; i < 8; ++i) { s += v[i]; q += v[i] * v[i]; }
    #pragma unroll
    for (int off = 16; off; off >>= 1) {
        s += __shfl_xor_sync(0xffffffffu, s, off);
        q += __shfl_xor_sync(0xffffffffu, q, off);
    }
    const float mu = s * (1.0f / DIMQ);
    const float rs = rsqrtf(q * (1.0f / DIMQ) - mu * mu + 1e-5f);

    float w[8], b[8];
    *(float4*)&w[0] = *(const float4*)(lw + lane * 8);
    *(float4*)&w[4] = *(const float4*)(lw + lane * 8 + 4);
    *(float4*)&b[0] = *(const float4*)(lb + lane * 8);
    *(float4*)&b[4] = *(const float4*)(lb + lane * 8 + 4);

    __nv_bfloat16 hi[8], lo[8];
    #pragma unroll
    for (int i = 0; i < 8; ++i) {
        const float y = (v[i] - mu) * rs * w[i] + b[i];
        hi[i] = __float2bfloat16(y);
        lo[i] = __float2bfloat16(y - __bfloat162float(hi[i]));
    }
    const size_t o = (size_t)warp * KDIM + lane * 8;
    *(uint4*)(g_xhi + o) = *(uint4*)hi;
    *(uint4*)(g_xlo + o) = *(uint4*)lo;
}

// ---------------------------------------------------------------------------
// Weight prep: Bt[n][k] = w[k][n], bf16 hi/lo.
// ---------------------------------------------------------------------------
__global__ void wprep_kernel(const float* __restrict__ w,
                             __nv_bfloat16* __restrict__ bhi,
                             __nv_bfloat16* __restrict__ blo, int Ncd)
{
    const int i = blockIdx.x * blockDim.x + threadIdx.x;
    if (i >= Ncd * KDIM) return;
    const int n = i / KDIM;
    const int k = i - n * KDIM;
    const float v = w[(size_t)k * Ncd + n];
    const __nv_bfloat16 h = __float2bfloat16(v);
    bhi[i] = h;
    blo[i] = __float2bfloat16(v - __bfloat162float(h));
}

// ---------------------------------------------------------------------------
// Attention: one warp per (batch, head); emits bf16 hi/lo.
// bias idx(i,j) = (i>=1 && j>=1) ? i-j+6 : 13
// ---------------------------------------------------------------------------
__global__ void attn_kernel(const float* __restrict__ btab)
{
    const int gw   = (blockIdx.x * blockDim.x + threadIdx.x) >> 5;
    const int lane = threadIdx.x & 31;
    if (gw >= BATCH * HEADS) return;
    const int b = gw >> 3;
    const int h = gw & 7;

    const float* base = g_qkv + (size_t)b * NTOK * QKV_COLS + h * 32 + lane;

    float kv[8], vv[8];
    #pragma unroll
    for (int n = 0; n < 8; ++n) {
        kv[n] = base[n * QKV_COLS + 256];
        vv[n] = base[n * QKV_COLS + 512];
    }

    const float scale = 0.1767766952966369f;  // 32^-0.5

    #pragma unroll
    for (int i = 0; i < 8; ++i) {
        const float qv = base[i * QKV_COLS] * scale;
        float p[8];
        #pragma unroll
        for (int j = 0; j < 8; ++j) {
            float t = qv * kv[j];
            #pragma unroll
            for (int off = 16; off; off >>= 1)
                t += __shfl_xor_sync(0xffffffffu, t, off);
            const int idx = (i >= 1 && j >= 1) ? (i - j + 6) : 13;
            p[j] = t + btab[idx * HEADS + h];
        }
        float m = p[0];
        #pragma unroll
        for (int j = 1; j < 8; ++j) m = fmaxf(m, p[j]);
        float sm = 0.f;
        #pragma unroll
        for (int j = 0; j < 8; ++j) { p[j] = expf(p[j] - m); sm += p[j]; }
        const float inv = 1.0f / sm;
        float o = 0.f;
        #pragma unroll
        for (int j = 0; j < 8; ++j) o = fmaf(p[j], vv[j], o);
        o *= inv;
        const __nv_bfloat16 oh = __float2bfloat16(o);
        const size_t oo = ((size_t)b * NTOK + i) * KDIM + h * 32 + lane;
        g_ahi[oo] = oh;
        g_alo[oo] = __float2bfloat16(o - __bfloat162float(oh));
    }
}

// ---------------------------------------------------------------------------
// Launch. Inputs: 0:x 1:ln_w 2:ln_b 3:w_qkv 4:w_out 5:rel_bias_table 6:idx
// ---------------------------------------------------------------------------
extern "C" void kernel_launch(void* const* d_in, const int* in_sizes, int n_in,
                              void* d_out, int out_size)
{
    const float* x    = (const float*)d_in[0];
    const float* lw   = (const float*)d_in[1];
    const float* lb   = (const float*)d_in[2];
    const float* wqkv = (const float*)d_in[3];
    const float* wout = (const float*)d_in[4];
    const float* btab = (const float*)d_in[5];
    float* out = (float*)d_out;

    float* qkv = nullptr;
    __nv_bfloat16 *xhi = nullptr, *xlo = nullptr, *ahi = nullptr, *alo = nullptr;
    __nv_bfloat16 *wqh = nullptr, *wql = nullptr, *woh = nullptr, *wol = nullptr;
    cudaGetSymbolAddress((void**)&qkv, g_qkv);
    cudaGetSymbolAddress((void**)&xhi, g_xhi);
    cudaGetSymbolAddress((void**)&xlo, g_xlo);
    cudaGetSymbolAddress((void**)&ahi, g_ahi);
    cudaGetSymbolAddress((void**)&alo, g_alo);
    cudaGetSymbolAddress((void**)&wqh, g_wq_hi);
    cudaGetSymbolAddress((void**)&wql, g_wq_lo);
    cudaGetSymbolAddress((void**)&woh, g_wo_hi);
    cudaGetSymbolAddress((void**)&wol, g_wo_lo);

    cudaFuncSetAttribute(gemm_mma, cudaFuncAttributeMaxDynamicSharedMemorySize,
                         GEMM_SMEM);

    // 1) LN + hi/lo split
    ln_split_kernel<<<32768, 256>>>(x, lw, lb);

    // 2) weight prep (tiny)
    wprep_kernel<<<(QKV_COLS * KDIM + 255) / 256, 256>>>(wqkv, wqh, wql, QKV_COLS);
    wprep_kernel<<<(DIMQ * KDIM + 255) / 256, 256>>>(wout, woh, wol, DIMQ);

    // 3) QKV GEMM: [262144,256] x [256,768] -> fp32
    {
        dim3 grid(QKV_COLS / 128, ROWS / 128);   // (6, 2048), x fastest -> L2 A reuse
        gemm_mma<<<grid, 256, GEMM_SMEM>>>(xhi, xlo, wqh, wql, qkv, QKV_COLS);
    }

    // 4) attention
    attn_kernel<<<32768, 256>>>(btab);

    // 5) output projection: [262144,256] x [256,256] -> d_out
    {
        dim3 grid(DIMQ / 128, ROWS / 128);       // (2, 2048)
        gemm_mma<<<grid, 256, GEMM_SMEM>>>(ahi, alo, woh, wol, out, DIMQ);
    }
}

// round 16
// speedup vs baseline: 2.6706x; 1.5080x over previous
#include <cuda_runtime.h>
#include <cuda_fp16.h>
#include <math.h>
#include <stdint.h>

// ---------------------------------------------------------------------------
// Attention1D on GB300 (sm_103 portable PTX path):
//   fp16 2-split GEMMs on mma.sync.m16n8k16 (HMMA, fp32 accum)
//   C = A_fp16 @ (Bhi + Blo),  B pre-scaled by 2^10 (epilogue x 2^-10)
//   A rounding error ~2^-12 rel; B split captures ~22 bits.
//   1) ln_half : LayerNorm(x) -> fp16                [262144,256]
//   2) wprep   : (w^T)*1024 -> fp16 hi/lo (K-major)  (tiny)
//   3) gemm    : qkv = xn @ w_qkv  -> fp32 [262144,768]
//   4) attn    : 8x8 windowed softmax + rel bias -> fp16
//   5) gemm    : out = att @ w_out -> fp32 [262144,256]
// ---------------------------------------------------------------------------

#define DIMQ      256
#define HEADS     8
#define NTOK      8
#define BATCH     32768
#define ROWS      (BATCH * NTOK)      // 262144
#define QKV_COLS  768
#define KDIM      256

#define WSCALE    1024.0f
#define INV_WSCALE 0.0009765625f      // 2^-10

// ----- scratch (device globals: allocation-free) -----
__device__ float   g_qkv[(size_t)ROWS * QKV_COLS];   // 805 MB fp32
__device__ __half  g_xh[(size_t)ROWS * KDIM];        // LN(x) fp16
__device__ __half  g_ah[(size_t)ROWS * KDIM];        // attention out fp16
__device__ __half  g_wq_hi[QKV_COLS * KDIM];         // (w_qkv^T)*1024 hi
__device__ __half  g_wq_lo[QKV_COLS * KDIM];
__device__ __half  g_wo_hi[DIMQ * KDIM];             // (w_out^T)*1024 hi
__device__ __half  g_wo_lo[DIMQ * KDIM];

// ---------------------------------------------------------------------------
// helpers
// ---------------------------------------------------------------------------
__device__ __forceinline__ uint32_t smem_u32(const void* p) {
    uint32_t a;
    asm("{ .reg .u64 t; cvta.to.shared.u64 t, %1; cvt.u32.u64 %0, t; }"
        : "=r"(a) : "l"(p));
    return a;
}

__device__ __forceinline__ void cp16(uint32_t dst, const void* src) {
    asm volatile("cp.async.cg.shared.global [%0], [%1], 16;"
                 :: "r"(dst), "l"(src) : "memory");
}

#define LDSM4(r0, r1, r2, r3, addr)                                            \
    asm volatile("ldmatrix.sync.aligned.m8n8.x4.shared.b16 {%0,%1,%2,%3}, [%4];" \
                 : "=r"(r0), "=r"(r1), "=r"(r2), "=r"(r3) : "r"(addr))

#define MMA16816(d, a0, a1, a2, a3, b0, b1)                                    \
    asm volatile("mma.sync.aligned.m16n8k16.row.col.f32.f16.f16.f32 "          \
                 "{%0,%1,%2,%3}, {%4,%5,%6,%7}, {%8,%9}, {%0,%1,%2,%3};"       \
                 : "+f"((d)[0]), "+f"((d)[1]), "+f"((d)[2]), "+f"((d)[3])      \
                 : "r"(a0), "r"(a1), "r"(a2), "r"(a3), "r"(b0), "r"(b1))

// ---------------------------------------------------------------------------
// GEMM: C[128x128 tile] = A_fp16[*,256] @ (Bhi+Blo)^T (B K-major, stride KDIM),
// fp32 output scaled by 2^-10. 256 threads = 8 warps (2 row x 4 col),
// warp tile 64x32. BK=32, double-buffered cp.async, 80B-padded smem rows
// (conflict-free ldmatrix). 3 operand tiles/stage: A, Bhi, Blo.
// ---------------------------------------------------------------------------
#define SROWB     80                       // smem row stride (bytes); 64B data
#define TILE_B    (128 * SROWB)            // 10240 B
#define STAGE_B   (3 * TILE_B)             // 30720 B
#define GEMM_SMEM (2 * STAGE_B)            // 61440 B -> 2 CTAs/SM

__global__ void __launch_bounds__(256, 2)
gemm_mma(const __half* __restrict__ A,
         const __half* __restrict__ Bhi, const __half* __restrict__ Blo,
         float* __restrict__ C, int Nc)
{
    extern __shared__ __align__(128) char smem[];
    const int tid  = threadIdx.x;
    const int lane = tid & 31;
    const int wid  = tid >> 5;
    const int warp_m = (wid & 1) * 64;
    const int warp_n = (wid >> 1) * 32;
    const uint32_t sb = smem_u32(smem);

    const size_t brow = (size_t)blockIdx.y * 128;
    const size_t bcol = (size_t)blockIdx.x * 128;

    const char* gA  = (const char*)(A   + brow * KDIM);
    const char* gBh = (const char*)(Bhi + bcol * KDIM);
    const char* gBl = (const char*)(Blo + bcol * KDIM);

    // cp.async mapping: per tile 512 16B-chunks (128 rows x 4), 2 per thread
    const int c0 = tid,        r0 = c0 >> 2, h0 = c0 & 3;
    const int c1 = tid + 256,  r1 = c1 >> 2, h1 = c1 & 3;
    const uint32_t sof0 = (uint32_t)(r0 * SROWB + h0 * 16);
    const uint32_t sof1 = (uint32_t)(r1 * SROWB + h1 * 16);
    const size_t   gof0 = (size_t)r0 * (KDIM * 2) + h0 * 16;
    const size_t   gof1 = (size_t)r1 * (KDIM * 2) + h1 * 16;

    float acc[4][4][4];
    #pragma unroll
    for (int i = 0; i < 4; ++i)
        #pragma unroll
        for (int j = 0; j < 4; ++j)
            #pragma unroll
            for (int r = 0; r < 4; ++r) acc[i][j][r] = 0.f;

    // ---- prologue: stage 0 (k bytes 0..63) ----
    {
        const uint32_t s = sb;
        cp16(s + 0*TILE_B + sof0, gA  + gof0);  cp16(s + 0*TILE_B + sof1, gA  + gof1);
        cp16(s + 1*TILE_B + sof0, gBh + gof0);  cp16(s + 1*TILE_B + sof1, gBh + gof1);
        cp16(s + 2*TILE_B + sof0, gBl + gof0);  cp16(s + 2*TILE_B + sof1, gBl + gof1);
        asm volatile("cp.async.commit_group;" ::: "memory");
    }

    int buf = 0;
    for (int kt = 0; kt < 8; ++kt) {
        asm volatile("cp.async.wait_group 0;" ::: "memory");
        __syncthreads();

        if (kt < 7) {
            const uint32_t s = sb + (buf ^ 1) * STAGE_B;
            const size_t ko = (size_t)(kt + 1) * 64;
            cp16(s + 0*TILE_B + sof0, gA  + gof0 + ko);  cp16(s + 0*TILE_B + sof1, gA  + gof1 + ko);
            cp16(s + 1*TILE_B + sof0, gBh + gof0 + ko);  cp16(s + 1*TILE_B + sof1, gBh + gof1 + ko);
            cp16(s + 2*TILE_B + sof0, gBl + gof0 + ko);  cp16(s + 2*TILE_B + sof1, gBl + gof1 + ko);
            asm volatile("cp.async.commit_group;" ::: "memory");
        }

        const uint32_t sbase = sb + buf * STAGE_B;

        #pragma unroll
        for (int ks = 0; ks < 2; ++ks) {
            uint32_t bh[4][2], bl[4][2];
            #pragma unroll
            for (int p = 0; p < 2; ++p) {
                const int g   = lane >> 3;
                const int row = warp_n + p * 16 + (g >> 1) * 8 + (lane & 7);
                const int chk = 2 * ks + (g & 1);
                const uint32_t a = sbase + 1*TILE_B + row * SROWB + chk * 16;
                LDSM4(bh[2*p][0], bh[2*p][1], bh[2*p+1][0], bh[2*p+1][1], a);
                LDSM4(bl[2*p][0], bl[2*p][1], bl[2*p+1][0], bl[2*p+1][1], a + TILE_B);
            }
            #pragma unroll
            for (int mt = 0; mt < 4; ++mt) {
                const int row = warp_m + mt * 16 + (lane & 15);
                const int chk = 2 * ks + (lane >> 4);
                const uint32_t a = sbase + row * SROWB + chk * 16;
                uint32_t a0, a1, a2, a3;
                LDSM4(a0, a1, a2, a3, a);
                #pragma unroll
                for (int nt = 0; nt < 4; ++nt) {
                    MMA16816(acc[mt][nt], a0, a1, a2, a3, bh[nt][0], bh[nt][1]);
                    MMA16816(acc[mt][nt], a0, a1, a2, a3, bl[nt][0], bl[nt][1]);
                }
            }
        }
        buf ^= 1;
    }

    // ---- epilogue (undo 2^10 weight pre-scale) ----
    float* Cw = C + (brow + warp_m) * (size_t)Nc + bcol + warp_n;
    const int gr = lane >> 2;
    const int gc = (lane & 3) * 2;
    #pragma unroll
    for (int mt = 0; mt < 4; ++mt) {
        #pragma unroll
        for (int nt = 0; nt < 4; ++nt) {
            float* p0 = Cw + (size_t)(mt * 16 + gr) * Nc + nt * 8 + gc;
            *(float2*)p0            = make_float2(acc[mt][nt][0] * INV_WSCALE,
                                                  acc[mt][nt][1] * INV_WSCALE);
            *(float2*)(p0 + 8 * Nc) = make_float2(acc[mt][nt][2] * INV_WSCALE,
                                                  acc[mt][nt][3] * INV_WSCALE);
        }
    }
}

// ---------------------------------------------------------------------------
// LayerNorm -> fp16. One warp per 256-wide row.
// ---------------------------------------------------------------------------
__global__ void ln_half_kernel(const float* __restrict__ x,
                               const float* __restrict__ lw,
                               const float* __restrict__ lb)
{
    const int warp = (blockIdx.x * blockDim.x + threadIdx.x) >> 5;
    const int lane = threadIdx.x & 31;
    if (warp >= ROWS) return;

    const float* xr = x + (size_t)warp * DIMQ + lane * 8;
    float v[8];
    *(float4*)&v[0] = *(const float4*)xr;
    *(float4*)&v[4] = *(const float4*)(xr + 4);

    float s = 0.f, q = 0.f;
    #pragma unroll
    for (int i = 0; i < 8; ++i) { s += v[i]; q += v[i] * v[i]; }
    #pragma unroll
    for (int off = 16; off; off >>= 1) {
        s += __shfl_xor_sync(0xffffffffu, s, off);
        q += __shfl_xor_sync(0xffffffffu, q, off);
    }
    const float mu = s * (1.0f / DIMQ);
    const float rs = rsqrtf(q * (1.0f / DIMQ) - mu * mu + 1e-5f);

    float w[8], b[8];
    *(float4*)&w[0] = *(const float4*)(lw + lane * 8);
    *(float4*)&w[4] = *(const float4*)(lw + lane * 8 + 4);
    *(float4*)&b[0] = *(const float4*)(lb + lane * 8);
    *(float4*)&b[4] = *(const float4*)(lb + lane * 8 + 4);

    __half hv[8];
    #pragma unroll
    for (int i = 0; i < 8; ++i)
        hv[i] = __float2half((v[i] - mu) * rs * w[i] + b[i]);
    *(uint4*)(g_xh + (size_t)warp * KDIM + lane * 8) = *(uint4*)hv;
}

// ---------------------------------------------------------------------------
// Weight prep: Bt[n][k] = w[k][n] * 1024, fp16 hi/lo.
// ---------------------------------------------------------------------------
__global__ void wprep_kernel(const float* __restrict__ w,
                             __half* __restrict__ bhi,
                             __half* __restrict__ blo, int Ncd)
{
    const int i = blockIdx.x * blockDim.x + threadIdx.x;
    if (i >= Ncd * KDIM) return;
    const int n = i / KDIM;
    const int k = i - n * KDIM;
    const float v = w[(size_t)k * Ncd + n] * WSCALE;
    const __half h = __float2half(v);
    bhi[i] = h;
    blo[i] = __float2half(v - __half2float(h));
}

// ---------------------------------------------------------------------------
// Attention: one warp per (batch, head); emits fp16.
// bias idx(i,j) = (i>=1 && j>=1) ? i-j+6 : 13
// ---------------------------------------------------------------------------
__global__ void attn_kernel(const float* __restrict__ btab)
{
    const int gw   = (blockIdx.x * blockDim.x + threadIdx.x) >> 5;
    const int lane = threadIdx.x & 31;
    if (gw >= BATCH * HEADS) return;
    const int b = gw >> 3;
    const int h = gw & 7;

    const float* base = g_qkv + (size_t)b * NTOK * QKV_COLS + h * 32 + lane;

    float kv[8], vv[8];
    #pragma unroll
    for (int n = 0; n < 8; ++n) {
        kv[n] = base[n * QKV_COLS + 256];
        vv[n] = base[n * QKV_COLS + 512];
    }

    const float scale = 0.1767766952966369f;  // 32^-0.5

    #pragma unroll
    for (int i = 0; i < 8; ++i) {
        const float qv = base[i * QKV_COLS] * scale;
        float p[8];
        #pragma unroll
        for (int j = 0; j < 8; ++j) {
            float t = qv * kv[j];
            #pragma unroll
            for (int off = 16; off; off >>= 1)
                t += __shfl_xor_sync(0xffffffffu, t, off);
            const int idx = (i >= 1 && j >= 1) ? (i - j + 6) : 13;
            p[j] = t + btab[idx * HEADS + h];
        }
        float m = p[0];
        #pragma unroll
        for (int j = 1; j < 8; ++j) m = fmaxf(m, p[j]);
        float sm = 0.f;
        #pragma unroll
        for (int j = 0; j < 8; ++j) { p[j] = expf(p[j] - m); sm += p[j]; }
        const float inv = 1.0f / sm;
        float o = 0.f;
        #pragma unroll
        for (int j = 0; j < 8; ++j) o = fmaf(p[j], vv[j], o);
        g_ah[((size_t)b * NTOK + i) * KDIM + h * 32 + lane] = __float2half(o * inv);
    }
}

// ---------------------------------------------------------------------------
// Launch. Inputs: 0:x 1:ln_w 2:ln_b 3:w_qkv 4:w_out 5:rel_bias_table 6:idx
// ---------------------------------------------------------------------------
extern "C" void kernel_launch(void* const* d_in, const int* in_sizes, int n_in,
                              void* d_out, int out_size)
{
    const float* x    = (const float*)d_in[0];
    const float* lw   = (const float*)d_in[1];
    const float* lb   = (const float*)d_in[2];
    const float* wqkv = (const float*)d_in[3];
    const float* wout = (const float*)d_in[4];
    const float* btab = (const float*)d_in[5];
    float* out = (float*)d_out;

    float* qkv = nullptr;
    __half *xh = nullptr, *ah = nullptr;
    __half *wqh = nullptr, *wql = nullptr, *woh = nullptr, *wol = nullptr;
    cudaGetSymbolAddress((void**)&qkv, g_qkv);
    cudaGetSymbolAddress((void**)&xh,  g_xh);
    cudaGetSymbolAddress((void**)&ah,  g_ah);
    cudaGetSymbolAddress((void**)&wqh, g_wq_hi);
    cudaGetSymbolAddress((void**)&wql, g_wq_lo);
    cudaGetSymbolAddress((void**)&woh, g_wo_hi);
    cudaGetSymbolAddress((void**)&wol, g_wo_lo);

    cudaFuncSetAttribute(gemm_mma, cudaFuncAttributeMaxDynamicSharedMemorySize,
                         GEMM_SMEM);

    // 1) LN -> fp16
    ln_half_kernel<<<32768, 256>>>(x, lw, lb);

    // 2) weight prep (tiny)
    wprep_kernel<<<(QKV_COLS * KDIM + 255) / 256, 256>>>(wqkv, wqh, wql, QKV_COLS);
    wprep_kernel<<<(DIMQ * KDIM + 255) / 256, 256>>>(wout, woh, wol, DIMQ);

    // 3) QKV GEMM: [262144,256] x [256,768] -> fp32
    {
        dim3 grid(QKV_COLS / 128, ROWS / 128);   // (6, 2048)
        gemm_mma<<<grid, 256, GEMM_SMEM>>>(xh, wqh, wql, qkv, QKV_COLS);
    }

    // 4) attention
    attn_kernel<<<32768, 256>>>(btab);

    // 5) output projection: [262144,256] x [256,256] -> d_out
    {
        dim3 grid(DIMQ / 128, ROWS / 128);       // (2, 2048)
        gemm_mma<<<grid, 256, GEMM_SMEM>>>(ah, woh, wol, out, DIMQ);
    }
}

// round 17
// speedup vs baseline: 2.6917x; 1.0079x over previous
#include <cuda_runtime.h>
#include <cuda_fp16.h>
#include <math.h>
#include <stdint.h>

// ---------------------------------------------------------------------------
// Attention1D on GB300 (sm_103 portable PTX path):
//   fp16 2-split GEMMs on mma.sync.m16n8k16 (HMMA, fp32 accum)
//   C = A_fp16 @ (Bhi + Blo),  B pre-scaled by 2^10 (epilogue x 2^-10)
//   1) ln_half : LayerNorm(x) -> fp16                 [262144,256]
//   2) wprep   : (w^T)*1024 -> fp16 hi/lo (K-major)   (tiny)
//   3) gemm    : qkv = xn @ w_qkv  -> fp16 [262144,768]
//   4) attn    : 8x8 windowed softmax + rel bias -> fp16
//   5) gemm    : out = att @ w_out -> fp32 [262144,256]
// GEMM: 128x128 tile, 8 warps (2x4), 3-stage cp.async pipeline, BK=32.
// ---------------------------------------------------------------------------

#define DIMQ      256
#define HEADS     8
#define NTOK      8
#define BATCH     32768
#define ROWS      (BATCH * NTOK)      // 262144
#define QKV_COLS  768
#define KDIM      256

#define WSCALE     1024.0f
#define INV_WSCALE 0.0009765625f      // 2^-10

// ----- scratch (device globals: allocation-free) -----
__device__ __half  g_qkv[(size_t)ROWS * QKV_COLS];   // 402 MB fp16
__device__ __half  g_xh[(size_t)ROWS * KDIM];        // LN(x) fp16
__device__ __half  g_ah[(size_t)ROWS * KDIM];        // attention out fp16
__device__ __half  g_wq_hi[QKV_COLS * KDIM];         // (w_qkv^T)*1024 hi
__device__ __half  g_wq_lo[QKV_COLS * KDIM];
__device__ __half  g_wo_hi[DIMQ * KDIM];             // (w_out^T)*1024 hi
__device__ __half  g_wo_lo[DIMQ * KDIM];

// ---------------------------------------------------------------------------
// helpers
// ---------------------------------------------------------------------------
__device__ __forceinline__ uint32_t smem_u32(const void* p) {
    uint32_t a;
    asm("{ .reg .u64 t; cvta.to.shared.u64 t, %1; cvt.u32.u64 %0, t; }"
        : "=r"(a) : "l"(p));
    return a;
}

__device__ __forceinline__ void cp16(uint32_t dst, const void* src) {
    asm volatile("cp.async.cg.shared.global [%0], [%1], 16;"
                 :: "r"(dst), "l"(src) : "memory");
}

#define LDSM4(r0, r1, r2, r3, addr)                                            \
    asm volatile("ldmatrix.sync.aligned.m8n8.x4.shared.b16 {%0,%1,%2,%3}, [%4];" \
                 : "=r"(r0), "=r"(r1), "=r"(r2), "=r"(r3) : "r"(addr))

#define MMA16816(d, a0, a1, a2, a3, b0, b1)                                    \
    asm volatile("mma.sync.aligned.m16n8k16.row.col.f32.f16.f16.f32 "          \
                 "{%0,%1,%2,%3}, {%4,%5,%6,%7}, {%8,%9}, {%0,%1,%2,%3};"       \
                 : "+f"((d)[0]), "+f"((d)[1]), "+f"((d)[2]), "+f"((d)[3])      \
                 : "r"(a0), "r"(a1), "r"(a2), "r"(a3), "r"(b0), "r"(b1))

// ---------------------------------------------------------------------------
// GEMM: C[128x128 tile] = A_fp16[*,256] @ (Bhi+Blo)^T (B K-major, stride KDIM),
// output scaled by 2^-10 (fp32 or fp16 via OutT). 256 threads = 8 warps
// (2 row x 4 col), warp tile 64x32. BK=32, 3-stage cp.async pipeline,
// 80B-padded smem rows (conflict-free ldmatrix). Tiles/stage: A, Bhi, Blo.
// ---------------------------------------------------------------------------
#define SROWB     80                       // smem row stride (bytes); 64B data
#define TILE_B    (128 * SROWB)            // 10240 B
#define STAGE_B   (3 * TILE_B)             // 30720 B
#define NSTAGE    3
#define GEMM_SMEM (NSTAGE * STAGE_B)       // 92160 B -> 2 CTAs/SM (180 KB)

template <typename OutT>
__global__ void __launch_bounds__(256, 2)
gemm_mma(const __half* __restrict__ A,
         const __half* __restrict__ Bhi, const __half* __restrict__ Blo,
         OutT* __restrict__ C, int Nc)
{
    extern __shared__ __align__(128) char smem[];
    const int tid  = threadIdx.x;
    const int lane = tid & 31;
    const int wid  = tid >> 5;
    const int warp_m = (wid & 1) * 64;
    const int warp_n = (wid >> 1) * 32;
    const uint32_t sb = smem_u32(smem);

    const size_t brow = (size_t)blockIdx.y * 128;
    const size_t bcol = (size_t)blockIdx.x * 128;

    const char* gA  = (const char*)(A   + brow * KDIM);
    const char* gBh = (const char*)(Bhi + bcol * KDIM);
    const char* gBl = (const char*)(Blo + bcol * KDIM);

    // cp.async mapping: per tile 512 16B-chunks (128 rows x 4), 2 per thread
    const int c0 = tid,        r0 = c0 >> 2, h0 = c0 & 3;
    const int c1 = tid + 256,  r1 = c1 >> 2, h1 = c1 & 3;
    const uint32_t sof0 = (uint32_t)(r0 * SROWB + h0 * 16);
    const uint32_t sof1 = (uint32_t)(r1 * SROWB + h1 * 16);
    const size_t   gof0 = (size_t)r0 * (KDIM * 2) + h0 * 16;
    const size_t   gof1 = (size_t)r1 * (KDIM * 2) + h1 * 16;

    float acc[4][4][4];
    #pragma unroll
    for (int i = 0; i < 4; ++i)
        #pragma unroll
        for (int j = 0; j < 4; ++j)
            #pragma unroll
            for (int r = 0; r < 4; ++r) acc[i][j][r] = 0.f;

    // ---- prologue: stages 0 and 1 ----
    #pragma unroll
    for (int st = 0; st < 2; ++st) {
        const uint32_t s = sb + st * STAGE_B;
        const size_t ko = (size_t)st * 64;
        cp16(s + 0*TILE_B + sof0, gA  + gof0 + ko);  cp16(s + 0*TILE_B + sof1, gA  + gof1 + ko);
        cp16(s + 1*TILE_B + sof0, gBh + gof0 + ko);  cp16(s + 1*TILE_B + sof1, gBh + gof1 + ko);
        cp16(s + 2*TILE_B + sof0, gBl + gof0 + ko);  cp16(s + 2*TILE_B + sof1, gBl + gof1 + ko);
        asm volatile("cp.async.commit_group;" ::: "memory");
    }

    int sidx = 0;
    for (int kt = 0; kt < 8; ++kt) {
        asm volatile("cp.async.wait_group 1;" ::: "memory");
        __syncthreads();   // stage kt visible; stage (kt+2)%3 free of readers

        if (kt < 6) {
            int wst = sidx + 2; if (wst >= NSTAGE) wst -= NSTAGE;
            const uint32_t s = sb + wst * STAGE_B;
            const size_t ko = (size_t)(kt + 2) * 64;
            cp16(s + 0*TILE_B + sof0, gA  + gof0 + ko);  cp16(s + 0*TILE_B + sof1, gA  + gof1 + ko);
            cp16(s + 1*TILE_B + sof0, gBh + gof0 + ko);  cp16(s + 1*TILE_B + sof1, gBh + gof1 + ko);
            cp16(s + 2*TILE_B + sof0, gBl + gof0 + ko);  cp16(s + 2*TILE_B + sof1, gBl + gof1 + ko);
        }
        asm volatile("cp.async.commit_group;" ::: "memory");  // keep group count uniform

        const uint32_t sbase = sb + sidx * STAGE_B;

        #pragma unroll
        for (int ks = 0; ks < 2; ++ks) {
            uint32_t bh[4][2], bl[4][2];
            #pragma unroll
            for (int p = 0; p < 2; ++p) {
                const int g   = lane >> 3;
                const int row = warp_n + p * 16 + (g >> 1) * 8 + (lane & 7);
                const int chk = 2 * ks + (g & 1);
                const uint32_t a = sbase + 1*TILE_B + row * SROWB + chk * 16;
                LDSM4(bh[2*p][0], bh[2*p][1], bh[2*p+1][0], bh[2*p+1][1], a);
                LDSM4(bl[2*p][0], bl[2*p][1], bl[2*p+1][0], bl[2*p+1][1], a + TILE_B);
            }
            #pragma unroll
            for (int mt = 0; mt < 4; ++mt) {
                const int row = warp_m + mt * 16 + (lane & 15);
                const int chk = 2 * ks + (lane >> 4);
                const uint32_t a = sbase + row * SROWB + chk * 16;
                uint32_t a0, a1, a2, a3;
                LDSM4(a0, a1, a2, a3, a);
                #pragma unroll
                for (int nt = 0; nt < 4; ++nt) {
                    MMA16816(acc[mt][nt], a0, a1, a2, a3, bh[nt][0], bh[nt][1]);
                    MMA16816(acc[mt][nt], a0, a1, a2, a3, bl[nt][0], bl[nt][1]);
                }
            }
        }
        if (++sidx == NSTAGE) sidx = 0;
    }

    // ---- epilogue (undo 2^10 weight pre-scale) ----
    OutT* Cw = C + (brow + warp_m) * (size_t)Nc + bcol + warp_n;
    const int gr = lane >> 2;
    const int gc = (lane & 3) * 2;
    #pragma unroll
    for (int mt = 0; mt < 4; ++mt) {
        #pragma unroll
        for (int nt = 0; nt < 4; ++nt) {
            OutT* p0 = Cw + (size_t)(mt * 16 + gr) * Nc + nt * 8 + gc;
            if constexpr (sizeof(OutT) == 4) {
                *(float2*)p0 = make_float2(acc[mt][nt][0] * INV_WSCALE,
                                           acc[mt][nt][1] * INV_WSCALE);
                *(float2*)((float*)p0 + 8 * Nc) =
                    make_float2(acc[mt][nt][2] * INV_WSCALE,
                                acc[mt][nt][3] * INV_WSCALE);
            } else {
                *(__half2*)p0 = __floats2half2_rn(acc[mt][nt][0] * INV_WSCALE,
                                                  acc[mt][nt][1] * INV_WSCALE);
                *(__half2*)((__half*)p0 + 8 * Nc) =
                    __floats2half2_rn(acc[mt][nt][2] * INV_WSCALE,
                                      acc[mt][nt][3] * INV_WSCALE);
            }
        }
    }
}

// ---------------------------------------------------------------------------
// LayerNorm -> fp16. One warp per 256-wide row.
// ---------------------------------------------------------------------------
__global__ void ln_half_kernel(const float* __restrict__ x,
                               const float* __restrict__ lw,
                               const float* __restrict__ lb)
{
    const int warp = (blockIdx.x * blockDim.x + threadIdx.x) >> 5;
    const int lane = threadIdx.x & 31;
    if (warp >= ROWS) return;

    const float* xr = x + (size_t)warp * DIMQ + lane * 8;
    float v[8];
    *(float4*)&v[0] = *(const float4*)xr;
    *(float4*)&v[4] = *(const float4*)(xr + 4);

    float s = 0.f, q = 0.f;
    #pragma unroll
    for (int i = 0; i < 8; ++i) { s += v[i]; q += v[i] * v[i]; }
    #pragma unroll
    for (int off = 16; off; off >>= 1) {
        s += __shfl_xor_sync(0xffffffffu, s, off);
        q += __shfl_xor_sync(0xffffffffu, q, off);
    }
    const float mu = s * (1.0f / DIMQ);
    const float rs = rsqrtf(q * (1.0f / DIMQ) - mu * mu + 1e-5f);

    float w[8], b[8];
    *(float4*)&w[0] = *(const float4*)(lw + lane * 8);
    *(float4*)&w[4] = *(const float4*)(lw + lane * 8 + 4);
    *(float4*)&b[0] = *(const float4*)(lb + lane * 8);
    *(float4*)&b[4] = *(const float4*)(lb + lane * 8 + 4);

    __half hv[8];
    #pragma unroll
    for (int i = 0; i < 8; ++i)
        hv[i] = __float2half((v[i] - mu) * rs * w[i] + b[i]);
    *(uint4*)(g_xh + (size_t)warp * KDIM + lane * 8) = *(uint4*)hv;
}

// ---------------------------------------------------------------------------
// Weight prep: Bt[n][k] = w[k][n] * 1024, fp16 hi/lo.
// ---------------------------------------------------------------------------
__global__ void wprep_kernel(const float* __restrict__ w,
                             __half* __restrict__ bhi,
                             __half* __restrict__ blo, int Ncd)
{
    const int i = blockIdx.x * blockDim.x + threadIdx.x;
    if (i >= Ncd * KDIM) return;
    const int n = i / KDIM;
    const int k = i - n * KDIM;
    const float v = w[(size_t)k * Ncd + n] * WSCALE;
    const __half h = __float2half(v);
    bhi[i] = h;
    blo[i] = __float2half(v - __half2float(h));
}

// ---------------------------------------------------------------------------
// Attention: one warp per (batch, head); fp16 qkv in, fp16 out.
// bias idx(i,j) = (i>=1 && j>=1) ? i-j+6 : 13
// ---------------------------------------------------------------------------
__global__ void attn_kernel(const float* __restrict__ btab)
{
    const int gw   = (blockIdx.x * blockDim.x + threadIdx.x) >> 5;
    const int lane = threadIdx.x & 31;
    if (gw >= BATCH * HEADS) return;
    const int b = gw >> 3;
    const int h = gw & 7;

    const __half* base = g_qkv + (size_t)b * NTOK * QKV_COLS + h * 32 + lane;

    float kv[8], vv[8], qv[8];
    #pragma unroll
    for (int n = 0; n < 8; ++n) {
        qv[n] = __half2float(base[n * QKV_COLS]);
        kv[n] = __half2float(base[n * QKV_COLS + 256]);
        vv[n] = __half2float(base[n * QKV_COLS + 512]);
    }

    const float scale = 0.1767766952966369f;  // 32^-0.5

    #pragma unroll
    for (int i = 0; i < 8; ++i) {
        const float qs = qv[i] * scale;
        float p[8];
        #pragma unroll
        for (int j = 0; j < 8; ++j) {
            float t = qs * kv[j];
            #pragma unroll
            for (int off = 16; off; off >>= 1)
                t += __shfl_xor_sync(0xffffffffu, t, off);
            const int idx = (i >= 1 && j >= 1) ? (i - j + 6) : 13;
            p[j] = t + btab[idx * HEADS + h];
        }
        float m = p[0];
        #pragma unroll
        for (int j = 1; j < 8; ++j) m = fmaxf(m, p[j]);
        float sm = 0.f;
        #pragma unroll
        for (int j = 0; j < 8; ++j) { p[j] = expf(p[j] - m); sm += p[j]; }
        const float inv = 1.0f / sm;
        float o = 0.f;
        #pragma unroll
        for (int j = 0; j < 8; ++j) o = fmaf(p[j], vv[j], o);
        g_ah[((size_t)b * NTOK + i) * KDIM + h * 32 + lane] = __float2half(o * inv);
    }
}

// ---------------------------------------------------------------------------
// Launch. Inputs: 0:x 1:ln_w 2:ln_b 3:w_qkv 4:w_out 5:rel_bias_table 6:idx
// ---------------------------------------------------------------------------
extern "C" void kernel_launch(void* const* d_in, const int* in_sizes, int n_in,
                              void* d_out, int out_size)
{
    const float* x    = (const float*)d_in[0];
    const float* lw   = (const float*)d_in[1];
    const float* lb   = (const float*)d_in[2];
    const float* wqkv = (const float*)d_in[3];
    const float* wout = (const float*)d_in[4];
    const float* btab = (const float*)d_in[5];
    float* out = (float*)d_out;

    __half *qkv = nullptr, *xh = nullptr, *ah = nullptr;
    __half *wqh = nullptr, *wql = nullptr, *woh = nullptr, *wol = nullptr;
    cudaGetSymbolAddress((void**)&qkv, g_qkv);
    cudaGetSymbolAddress((void**)&xh,  g_xh);
    cudaGetSymbolAddress((void**)&ah,  g_ah);
    cudaGetSymbolAddress((void**)&wqh, g_wq_hi);
    cudaGetSymbolAddress((void**)&wql, g_wq_lo);
    cudaGetSymbolAddress((void**)&woh, g_wo_hi);
    cudaGetSymbolAddress((void**)&wol, g_wo_lo);

    cudaFuncSetAttribute(gemm_mma<__half>,
                         cudaFuncAttributeMaxDynamicSharedMemorySize, GEMM_SMEM);
    cudaFuncSetAttribute(gemm_mma<float>,
                         cudaFuncAttributeMaxDynamicSharedMemorySize, GEMM_SMEM);

    // 1) LN -> fp16
    ln_half_kernel<<<32768, 256>>>(x, lw, lb);

    // 2) weight prep (tiny)
    wprep_kernel<<<(QKV_COLS * KDIM + 255) / 256, 256>>>(wqkv, wqh, wql, QKV_COLS);
    wprep_kernel<<<(DIMQ * KDIM + 255) / 256, 256>>>(wout, woh, wol, DIMQ);

    // 3) QKV GEMM: [262144,256] x [256,768] -> fp16
    {
        dim3 grid(QKV_COLS / 128, ROWS / 128);   // (6, 2048)
        gemm_mma<__half><<<grid, 256, GEMM_SMEM>>>(xh, wqh, wql, qkv, QKV_COLS);
    }

    // 4) attention
    attn_kernel<<<32768, 256>>>(btab);

    // 5) output projection: [262144,256] x [256,256] -> d_out (fp32)
    {
        dim3 grid(DIMQ / 128, ROWS / 128);       // (2, 2048)
        gemm_mma<float><<<grid, 256, GEMM_SMEM>>>(ah, woh, wol, out, DIMQ);
    }
}